// round 16
// baseline (speedup 1.0000x reference)
#include <cuda_runtime.h>
#include <stdint.h>
#include <math.h>

// Problem constants
#define BATCH 2
#define SEQ   2048
#define HID   2048
#define NH    16
#define NKV   4
#define HD    128
#define ROT   64
#define NTOK  (BATCH*SEQ)      // 4096
#define QGN   (NH*HD*2)        // 4096  (q 2048 | gate 2048)
#define KVN   (NKV*HD)         // 512

// ---------------- scratch (device globals: allocation-free) ----------------
__device__ float g_qg[(size_t)NTOK * QGN];   // 64 MB : q | gate
__device__ float g_k [(size_t)NTOK * KVN];   //  8 MB (tf32-rounded bits)
__device__ float g_v [(size_t)NTOK * KVN];   //  8 MB (tf32-rounded bits)
__device__ float g_o [(size_t)NTOK * HID];   // 32 MB : attention out
__device__ float g_n [(size_t)NTOK * HID];   // 32 MB : rmsnorm*gate (tf32 bits)
// tf32-pre-rounded operand copies
__device__ float g_hsr[(size_t)NTOK * HID];  // 32 MB
__device__ float g_wqr[(size_t)HID * QGN];   // 32 MB
__device__ float g_wkr[(size_t)HID * KVN];   //  4 MB
__device__ float g_wvr[(size_t)HID * KVN];   //  4 MB
__device__ float g_wor[(size_t)HID * HID];   // 16 MB

__device__ __forceinline__ unsigned f2tf32(float x) {
    unsigned u;
    asm("cvt.rna.tf32.f32 %0, %1;" : "=r"(u) : "f"(x));
    return u;
}

__device__ __forceinline__ void cp16(unsigned dst, const void* src) {
    asm volatile("cp.async.cg.shared.global [%0], [%1], 16;\n"
                 :: "r"(dst), "l"(src));
}

#define MMA_TF32(d0,d1,d2,d3,a0,a1,a2,a3,b0,b1) \
    asm volatile( \
        "mma.sync.aligned.m16n8k8.row.col.f32.tf32.tf32.f32 " \
        "{%0,%1,%2,%3}, {%4,%5,%6,%7}, {%8,%9}, {%0,%1,%2,%3};\n" \
        : "+f"(d0), "+f"(d1), "+f"(d2), "+f"(d3) \
        : "r"(a0), "r"(a1), "r"(a2), "r"(a3), "r"(b0), "r"(b1))

// ---------------- tf32 pre-rounding (elementwise) --------------------------
__global__ __launch_bounds__(256) void round_kernel(const float* __restrict__ x,
                                                    float* __restrict__ y)
{
    size_t i = ((size_t)blockIdx.x * 256 + threadIdx.x) * 4;
    float4 v = *(const float4*)(x + i);
    v.x = __uint_as_float(f2tf32(v.x));
    v.y = __uint_as_float(f2tf32(v.y));
    v.z = __uint_as_float(f2tf32(v.z));
    v.w = __uint_as_float(f2tf32(v.w));
    *(float4*)(y + i) = v;
}

// =================== tf32 tensor-core GEMM: C = A[M,K] @ B[K,N] ============
// CTA 128x256x16, 8 warps (warp 64x64), 3-stage cp.async pipeline.
// Operands must be tf32-pre-rounded (fragments are raw-bit loads).
// blockIdx.z==1 switches to (B2, C2). rnd!=0 rounds output to tf32 bits.
#define TBM 128
#define TBN 256
#define TBK 16
#define NST 3
#define ASTR 20                       // As [m][k] row stride
#define BSTR 264                      // Bs [k][n] row stride (264%32==8)
#define AS_SZ (TBM * ASTR)            // 2560 floats
#define BS_SZ (TBK * BSTR)            // 4224 floats
#define STG_SZ (AS_SZ + BS_SZ)        // 6784 floats (27136 B, 16B-aligned)
#define GEMM_SMEM (NST * STG_SZ * 4)  // 81408 B

__global__ __launch_bounds__(256) void gemm_tf32(
    const float* __restrict__ A, const float* __restrict__ B,
    float* __restrict__ C, const float* __restrict__ B2,
    float* __restrict__ C2, int M, int N, int K, int rnd)
{
    extern __shared__ float gsm[];

    if (blockIdx.z == 1) { B = B2; C = C2; }

    const int tid    = threadIdx.x;
    const int lane   = tid & 31;
    const int wid    = tid >> 5;
    const int warp_m = (wid >> 2) * 64;     // 0, 64
    const int warp_n = (wid & 3)  * 64;     // 0,64,128,192
    const int grp    = lane >> 2;
    const int tg     = lane & 3;

    const int m0 = blockIdx.y * TBM;
    const int n0 = blockIdx.x * TBN;

    // loader coords: 2 A-chunks + 4 B-chunks of 16B per thread per stage
    const int ac0 = tid * 2;
    const int a_r0 = ac0 >> 2,      a_c0 = (ac0 & 3) * 4;
    const int a_r1 = (ac0+1) >> 2,  a_c1 = ((ac0+1) & 3) * 4;

    const unsigned smem_base = (unsigned)__cvta_generic_to_shared(gsm);

    float acc[4][8][4];
#pragma unroll
    for (int i = 0; i < 4; i++)
#pragma unroll
        for (int j = 0; j < 8; j++)
#pragma unroll
            for (int c = 0; c < 4; c++) acc[i][j][c] = 0.0f;

    const int niter = K / TBK;

#pragma unroll
    for (int s = 0; s < NST - 1; s++) {
        int k0 = s * TBK;
        unsigned as = smem_base + (s * STG_SZ) * 4;
        unsigned bs = as + AS_SZ * 4;
        cp16(as + (a_r0 * ASTR + a_c0) * 4, A + (size_t)(m0 + a_r0) * K + k0 + a_c0);
        cp16(as + (a_r1 * ASTR + a_c1) * 4, A + (size_t)(m0 + a_r1) * K + k0 + a_c1);
#pragma unroll
        for (int i = 0; i < 4; i++) {
            int bc = tid + i * 256;
            int br = bc >> 6, bcl = (bc & 63) * 4;
            cp16(bs + (br * BSTR + bcl) * 4, B + (size_t)(k0 + br) * N + n0 + bcl);
        }
        asm volatile("cp.async.commit_group;\n");
    }

    for (int it = 0; it < niter; it++) {
        if (it + NST - 1 < niter) {
            int k0 = (it + NST - 1) * TBK;
            int st = (it + NST - 1) % NST;
            unsigned as = smem_base + (st * STG_SZ) * 4;
            unsigned bs = as + AS_SZ * 4;
            cp16(as + (a_r0 * ASTR + a_c0) * 4, A + (size_t)(m0 + a_r0) * K + k0 + a_c0);
            cp16(as + (a_r1 * ASTR + a_c1) * 4, A + (size_t)(m0 + a_r1) * K + k0 + a_c1);
#pragma unroll
            for (int i = 0; i < 4; i++) {
                int bc = tid + i * 256;
                int br = bc >> 6, bcl = (bc & 63) * 4;
                cp16(bs + (br * BSTR + bcl) * 4, B + (size_t)(k0 + br) * N + n0 + bcl);
            }
        }
        asm volatile("cp.async.commit_group;\n");
        asm volatile("cp.async.wait_group 2;\n");
        __syncthreads();

        const float* As = gsm + (it % NST) * STG_SZ;
        const float* Bs = As + AS_SZ;

#pragma unroll
        for (int ks = 0; ks < TBK; ks += 8) {
            unsigned a[4][4], bfr[8][2];
#pragma unroll
            for (int mi = 0; mi < 4; mi++) {
                int mb = warp_m + mi * 16;
                a[mi][0] = __float_as_uint(As[(mb + grp)     * ASTR + ks + tg]);
                a[mi][1] = __float_as_uint(As[(mb + grp + 8) * ASTR + ks + tg]);
                a[mi][2] = __float_as_uint(As[(mb + grp)     * ASTR + ks + tg + 4]);
                a[mi][3] = __float_as_uint(As[(mb + grp + 8) * ASTR + ks + tg + 4]);
            }
#pragma unroll
            for (int nj = 0; nj < 8; nj++) {
                int nb = warp_n + nj * 8;
                bfr[nj][0] = __float_as_uint(Bs[(ks + tg)     * BSTR + nb + grp]);
                bfr[nj][1] = __float_as_uint(Bs[(ks + tg + 4) * BSTR + nb + grp]);
            }
#pragma unroll
            for (int mi = 0; mi < 4; mi++)
#pragma unroll
                for (int nj = 0; nj < 8; nj++)
                    MMA_TF32(acc[mi][nj][0], acc[mi][nj][1], acc[mi][nj][2], acc[mi][nj][3],
                             a[mi][0], a[mi][1], a[mi][2], a[mi][3],
                             bfr[nj][0], bfr[nj][1]);
        }
        __syncthreads();
    }

#pragma unroll
    for (int mi = 0; mi < 4; mi++)
#pragma unroll
        for (int nj = 0; nj < 8; nj++) {
            int row = m0 + warp_m + mi * 16 + grp;
            int col = n0 + warp_n + nj * 8 + 2 * tg;
            float v0 = acc[mi][nj][0], v1 = acc[mi][nj][1];
            float v2 = acc[mi][nj][2], v3 = acc[mi][nj][3];
            if (rnd) {
                v0 = __uint_as_float(f2tf32(v0));
                v1 = __uint_as_float(f2tf32(v1));
                v2 = __uint_as_float(f2tf32(v2));
                v3 = __uint_as_float(f2tf32(v3));
            }
            *(float2*)(C + (size_t)row * N + col)       = make_float2(v0, v1);
            *(float2*)(C + (size_t)(row + 8) * N + col) = make_float2(v2, v3);
        }
}

// ---------------- RoPE: warp-per-head, lane owns (j, j+32) pair ------------
__global__ __launch_bounds__(256) void rope_kernel(const float* __restrict__ cosb,
                                                   const float* __restrict__ sinb)
{
    const int t    = blockIdx.x;
    const int lane = threadIdx.x & 31;
    const int w    = threadIdx.x >> 5;

    const float c0 = cosb[(size_t)t * ROT + lane];
    const float c1 = cosb[(size_t)t * ROT + 32 + lane];
    const float s0 = sinb[(size_t)t * ROT + lane];
    const float s1 = sinb[(size_t)t * ROT + 32 + lane];

#pragma unroll
    for (int head = w; head < NH + NKV; head += 8) {
        float* base = (head < NH)
            ? g_qg + (size_t)t * QGN + head * HD
            : g_k  + (size_t)t * KVN + (head - NH) * HD;
        float x0 = base[lane];
        float x1 = base[lane + 32];
        float p0 = base[64 + lane];
        float p1 = base[96 + lane];
        float rh0 = -x1;
        float rh1 = x0;
        if (head < NH) {
            base[lane]      = c0 * p0 + rh0 * s0;
            base[lane + 32] = c1 * p1 + rh1 * s1;
        } else {
            base[lane]      = __uint_as_float(f2tf32(s0 * p0 + rh0 * s0));
            base[lane + 32] = __uint_as_float(f2tf32(s1 * p1 + rh1 * s1));
        }
    }
}

// =============== flash attention, tf32 tensor cores (R11, unchanged) =======
#define TSTR 136
#define QTILE (128 * TSTR)
#define KVTILE (64 * TSTR)
#define ATT_SMEM ((QTILE + 2 * 2 * KVTILE) * 4)   // 208896 B

__global__ __launch_bounds__(256) void attn_mma_kernel()
{
    extern __shared__ float sm[];

    const int qt  = (int)gridDim.x - 1 - (int)blockIdx.x;
    const int h   = blockIdx.y;
    const int b   = blockIdx.z;
    const int kvh = h / (NH / NKV);

    const int tid  = threadIdx.x;
    const int lane = tid & 31;
    const int wid  = tid >> 5;
    const int grp  = lane >> 2;
    const int tg   = lane & 3;
    const int wm   = wid * 16;

    const unsigned smb = (unsigned)__cvta_generic_to_shared(sm);
    const int njt = 2 * qt + 2;

    const float* Qb = g_qg + (size_t)(b * SEQ + qt * 128) * QGN + h * HD;
#pragma unroll
    for (int i = 0; i < 16; i++) {
        int c = tid + i * 256;
        int r = c >> 5;
        int cl = (c & 31) * 4;
        cp16(smb + (r * TSTR + cl) * 4, Qb + (size_t)r * QGN + cl);
    }
    {
        const float* Kb = g_k + (size_t)(b * SEQ) * KVN + kvh * HD;
        const float* Vb = g_v + (size_t)(b * SEQ) * KVN + kvh * HD;
#pragma unroll
        for (int i = 0; i < 8; i++) {
            int c = tid + i * 256;
            int r = c >> 5;
            int cl = (c & 31) * 4;
            cp16(smb + (QTILE + r * TSTR + cl) * 4,          Kb + (size_t)r * KVN + cl);
            cp16(smb + (QTILE + KVTILE + r * TSTR + cl) * 4, Vb + (size_t)r * KVN + cl);
        }
    }
    asm volatile("cp.async.commit_group;\n");

    float o[16][4];
#pragma unroll
    for (int nt = 0; nt < 16; nt++)
#pragma unroll
        for (int c = 0; c < 4; c++) o[nt][c] = 0.0f;
    float m0 = -1e30f, m1 = -1e30f, l0 = 0.0f, l1 = 0.0f;
    unsigned qf[16][4];

    const float scale = 0.08838834764831845f;
    const int row_g0 = qt * 128 + wm + grp;
    const int row_g1 = row_g0 + 8;
    const unsigned src_lo = (unsigned)((lane & ~3) | (tg >> 1));
    const unsigned src_hi = src_lo | 2u;
    const bool odd = (tg & 1);

    for (int jt = 0; jt < njt; jt++) {
        const int cs = jt & 1;
        if (jt + 1 < njt) {
            const int ns = 1 - cs;
            const float* Kb = g_k + (size_t)(b * SEQ + (jt + 1) * 64) * KVN + kvh * HD;
            const float* Vb = g_v + (size_t)(b * SEQ + (jt + 1) * 64) * KVN + kvh * HD;
            unsigned kofs = smb + (QTILE + ns * 2 * KVTILE) * 4;
#pragma unroll
            for (int i = 0; i < 8; i++) {
                int c = tid + i * 256;
                int r = c >> 5;
                int cl = (c & 31) * 4;
                cp16(kofs + (r * TSTR + cl) * 4,          Kb + (size_t)r * KVN + cl);
                cp16(kofs + (KVTILE + r * TSTR + cl) * 4, Vb + (size_t)r * KVN + cl);
            }
        }
        asm volatile("cp.async.commit_group;\n");
        asm volatile("cp.async.wait_group 1;\n");
        __syncthreads();

        const float* Ks = sm + QTILE + cs * 2 * KVTILE;
        const float* Vs = Ks + KVTILE;

        if (jt == 0) {
            const float* Qs = sm;
#pragma unroll
            for (int ks = 0; ks < 16; ks++) {
                int k0 = ks * 8;
                qf[ks][0] = f2tf32(Qs[(wm + grp)     * TSTR + k0 + tg]);
                qf[ks][1] = f2tf32(Qs[(wm + grp + 8) * TSTR + k0 + tg]);
                qf[ks][2] = f2tf32(Qs[(wm + grp)     * TSTR + k0 + tg + 4]);
                qf[ks][3] = f2tf32(Qs[(wm + grp + 8) * TSTR + k0 + tg + 4]);
            }
        }

        float s[8][4];
#pragma unroll
        for (int nt = 0; nt < 8; nt++)
#pragma unroll
            for (int c = 0; c < 4; c++) s[nt][c] = 0.0f;

#pragma unroll
        for (int ks = 0; ks < 16; ks++) {
            int k0 = ks * 8;
#pragma unroll
            for (int nt = 0; nt < 8; nt++) {
                unsigned b0 = __float_as_uint(Ks[(nt * 8 + grp) * TSTR + k0 + tg]);
                unsigned b1 = __float_as_uint(Ks[(nt * 8 + grp) * TSTR + k0 + tg + 4]);
                MMA_TF32(s[nt][0], s[nt][1], s[nt][2], s[nt][3],
                         qf[ks][0], qf[ks][1], qf[ks][2], qf[ks][3], b0, b1);
            }
        }

        const bool need_mask = (jt >= 2 * qt);
#pragma unroll
        for (int nt = 0; nt < 8; nt++) {
            s[nt][0] *= scale; s[nt][1] *= scale;
            s[nt][2] *= scale; s[nt][3] *= scale;
            if (need_mask) {
                int c0 = jt * 64 + nt * 8 + 2 * tg;
                if (c0     > row_g0) s[nt][0] = -1.0e9f;
                if (c0 + 1 > row_g0) s[nt][1] = -1.0e9f;
                if (c0     > row_g1) s[nt][2] = -1.0e9f;
                if (c0 + 1 > row_g1) s[nt][3] = -1.0e9f;
            }
        }

        float mx0 = -1e30f, mx1 = -1e30f;
#pragma unroll
        for (int nt = 0; nt < 8; nt++) {
            mx0 = fmaxf(mx0, fmaxf(s[nt][0], s[nt][1]));
            mx1 = fmaxf(mx1, fmaxf(s[nt][2], s[nt][3]));
        }
        mx0 = fmaxf(mx0, __shfl_xor_sync(0xffffffffu, mx0, 1));
        mx0 = fmaxf(mx0, __shfl_xor_sync(0xffffffffu, mx0, 2));
        mx1 = fmaxf(mx1, __shfl_xor_sync(0xffffffffu, mx1, 1));
        mx1 = fmaxf(mx1, __shfl_xor_sync(0xffffffffu, mx1, 2));

        float mn0 = fmaxf(m0, mx0);
        float mn1 = fmaxf(m1, mx1);
        float sc0 = __expf(m0 - mn0);
        float sc1 = __expf(m1 - mn1);
        float rs0 = 0.0f, rs1 = 0.0f;
#pragma unroll
        for (int nt = 0; nt < 8; nt++) {
            s[nt][0] = __expf(s[nt][0] - mn0);
            s[nt][1] = __expf(s[nt][1] - mn0);
            s[nt][2] = __expf(s[nt][2] - mn1);
            s[nt][3] = __expf(s[nt][3] - mn1);
            rs0 += s[nt][0] + s[nt][1];
            rs1 += s[nt][2] + s[nt][3];
        }
        rs0 += __shfl_xor_sync(0xffffffffu, rs0, 1);
        rs0 += __shfl_xor_sync(0xffffffffu, rs0, 2);
        rs1 += __shfl_xor_sync(0xffffffffu, rs1, 1);
        rs1 += __shfl_xor_sync(0xffffffffu, rs1, 2);

        l0 = l0 * sc0 + rs0; m0 = mn0;
        l1 = l1 * sc1 + rs1; m1 = mn1;
#pragma unroll
        for (int nt = 0; nt < 16; nt++) {
            o[nt][0] *= sc0; o[nt][1] *= sc0;
            o[nt][2] *= sc1; o[nt][3] *= sc1;
        }

        unsigned u[8][4];
#pragma unroll
        for (int nt = 0; nt < 8; nt++)
#pragma unroll
            for (int c = 0; c < 4; c++) u[nt][c] = f2tf32(s[nt][c]);

#pragma unroll
        for (int ks = 0; ks < 8; ks++) {
            unsigned t00 = __shfl_sync(0xffffffffu, u[ks][0], src_lo);
            unsigned t01 = __shfl_sync(0xffffffffu, u[ks][1], src_lo);
            unsigned a0  = odd ? t01 : t00;
            unsigned t10 = __shfl_sync(0xffffffffu, u[ks][2], src_lo);
            unsigned t11 = __shfl_sync(0xffffffffu, u[ks][3], src_lo);
            unsigned a1  = odd ? t11 : t10;
            unsigned t20 = __shfl_sync(0xffffffffu, u[ks][0], src_hi);
            unsigned t21 = __shfl_sync(0xffffffffu, u[ks][1], src_hi);
            unsigned a2  = odd ? t21 : t20;
            unsigned t30 = __shfl_sync(0xffffffffu, u[ks][2], src_hi);
            unsigned t31 = __shfl_sync(0xffffffffu, u[ks][3], src_hi);
            unsigned a3  = odd ? t31 : t30;
            int k0 = ks * 8;
#pragma unroll
            for (int nt = 0; nt < 16; nt++) {
                unsigned b0 = __float_as_uint(Vs[(k0 + tg)     * TSTR + nt * 8 + grp]);
                unsigned b1 = __float_as_uint(Vs[(k0 + tg + 4) * TSTR + nt * 8 + grp]);
                MMA_TF32(o[nt][0], o[nt][1], o[nt][2], o[nt][3], a0, a1, a2, a3, b0, b1);
            }
        }
        __syncthreads();
    }

    float inv0 = 1.0f / l0;
    float inv1 = 1.0f / l1;
#pragma unroll
    for (int nt = 0; nt < 16; nt++) {
        int col = h * HD + nt * 8 + 2 * tg;
        *(float2*)(g_o + (size_t)(b * SEQ + row_g0) * HID + col) =
            make_float2(o[nt][0] * inv0, o[nt][1] * inv0);
        *(float2*)(g_o + (size_t)(b * SEQ + row_g1) * HID + col) =
            make_float2(o[nt][2] * inv1, o[nt][3] * inv1);
    }
}

// ------ rmsnorm * (1+w) * sigmoid(gate); output tf32-rounded ---------------
__global__ __launch_bounds__(256) void norm_gate_kernel(const float* __restrict__ nw)
{
    const int t   = blockIdx.x;
    const int tid = threadIdx.x;
    const float* o    = g_o  + (size_t)t * HID;
    const float* gate = g_qg + (size_t)t * QGN + 2048;

    float vals[8];
    float ss = 0.0f;
#pragma unroll
    for (int i = 0; i < 8; i++) {
        float v = o[tid + i * 256];
        vals[i] = v;
        ss += v * v;
    }
#pragma unroll
    for (int off = 16; off >= 1; off >>= 1)
        ss += __shfl_xor_sync(0xffffffffu, ss, off);

    __shared__ float red[8];
    if ((tid & 31) == 0) red[tid >> 5] = ss;
    __syncthreads();
    float tot = red[0] + red[1] + red[2] + red[3] + red[4] + red[5] + red[6] + red[7];
    float r = rsqrtf(tot / (float)HID + 1e-6f);

#pragma unroll
    for (int i = 0; i < 8; i++) {
        int j = tid + i * 256;
        float gt = gate[j];
        float sg = 1.0f / (1.0f + __expf(-gt));
        g_n[(size_t)t * HID + j] =
            __uint_as_float(f2tf32(vals[i] * r * (1.0f + nw[j]) * sg));
    }
}

// ---------------- launch ---------------------------------------------------
extern "C" void kernel_launch(void* const* d_in, const int* in_sizes, int n_in,
                              void* d_out, int out_size)
{
    const float* hs   = (const float*)d_in[0];
    const float* cosb = (const float*)d_in[1];
    const float* sinb = (const float*)d_in[2];
    // d_in[3] = attention_mask (causal, reproduced analytically)
    const float* Wq   = (const float*)d_in[4];
    const float* Wk   = (const float*)d_in[5];
    const float* Wv   = (const float*)d_in[6];
    const float* Wo   = (const float*)d_in[7];
    const float* nw   = (const float*)d_in[8];
    float* out = (float*)d_out;

    float *qg, *kb, *vb, *nb, *hsr, *wqr, *wkr, *wvr, *wor;
    cudaGetSymbolAddress((void**)&qg,  g_qg);
    cudaGetSymbolAddress((void**)&kb,  g_k);
    cudaGetSymbolAddress((void**)&vb,  g_v);
    cudaGetSymbolAddress((void**)&nb,  g_n);
    cudaGetSymbolAddress((void**)&hsr, g_hsr);
    cudaGetSymbolAddress((void**)&wqr, g_wqr);
    cudaGetSymbolAddress((void**)&wkr, g_wkr);
    cudaGetSymbolAddress((void**)&wvr, g_wvr);
    cudaGetSymbolAddress((void**)&wor, g_wor);

    dim3 blk(256);

    cudaFuncSetAttribute(gemm_tf32, cudaFuncAttributeMaxDynamicSharedMemorySize, GEMM_SMEM);
    cudaFuncSetAttribute(attn_mma_kernel, cudaFuncAttributeMaxDynamicSharedMemorySize, ATT_SMEM);

    // 0) pre-round operands to tf32 bits (bit-identical to cvt-at-load)
    round_kernel<<<(NTOK * (size_t)HID) / 1024, blk>>>(hs, hsr);
    round_kernel<<<((size_t)HID * QGN) / 1024, blk>>>(Wq, wqr);
    round_kernel<<<((size_t)HID * KVN) / 1024, blk>>>(Wk, wkr);
    round_kernel<<<((size_t)HID * KVN) / 1024, blk>>>(Wv, wvr);
    round_kernel<<<((size_t)HID * HID) / 1024, blk>>>(Wo, wor);

    // 1) projections (raw-bit tf32 fragments); KV outputs tf32-rounded
    gemm_tf32<<<dim3(QGN / TBN, NTOK / TBM, 1), blk, GEMM_SMEM>>>(
        hsr, wqr, qg, wqr, qg, NTOK, QGN, HID, 0);
    gemm_tf32<<<dim3(KVN / TBN, NTOK / TBM, 2), blk, GEMM_SMEM>>>(
        hsr, wkr, kb, wvr, vb, NTOK, KVN, HID, 1);

    // 2) rope (K outputs tf32-rounded)
    rope_kernel<<<NTOK, blk>>>(cosb, sinb);

    // 3) flash attention
    attn_mma_kernel<<<dim3(SEQ / 128, NH, BATCH), blk, ATT_SMEM>>>();

    // 4) rmsnorm * sigmoid(gate), tf32-rounded output
    norm_gate_kernel<<<NTOK, blk>>>(nw);

    // 5) output projection
    gemm_tf32<<<dim3(HID / TBN, NTOK / TBM, 1), blk, GEMM_SMEM>>>(
        nb, wor, out, wor, out, NTOK, HID, HID, 0);
}

// round 17
// speedup vs baseline: 1.3818x; 1.3818x over previous
#include <cuda_runtime.h>
#include <cuda_fp16.h>
#include <stdint.h>
#include <math.h>

// Problem constants
#define BATCH 2
#define SEQ   2048
#define HID   2048
#define NH    16
#define NKV   4
#define HD    128
#define ROT   64
#define NTOK  (BATCH*SEQ)      // 4096
#define QGN   (NH*HD*2)        // 4096  (q 2048 | gate 2048)
#define KVN   (NKV*HD)         // 512

// ---------------- scratch (device globals: allocation-free) ----------------
__device__ float g_qg[(size_t)NTOK * QGN];   // 64 MB : q | gate
__device__ float g_k [(size_t)NTOK * KVN];   //  8 MB (tf32-rounded bits)
__device__ float g_v [(size_t)NTOK * KVN];   //  8 MB (tf32-rounded bits)
__device__ float g_o [(size_t)NTOK * HID];   // 32 MB : attention out
// fp16 operands
__device__ __half g_hsh[(size_t)NTOK * HID];   // 16 MB : hs as half [M][K]
__device__ __half g_wqt[(size_t)QGN * HID];    // 16 MB : Wq^T [N][K]
__device__ __half g_wkt[(size_t)KVN * HID];    //  2 MB
__device__ __half g_wvt[(size_t)KVN * HID];    //  2 MB
__device__ __half g_wot[(size_t)HID * HID];    //  8 MB
__device__ __half g_nh [(size_t)NTOK * HID];   // 16 MB : rmsnorm*gate as half

__device__ __forceinline__ unsigned f2tf32(float x) {
    unsigned u;
    asm("cvt.rna.tf32.f32 %0, %1;" : "=r"(u) : "f"(x));
    return u;
}

__device__ __forceinline__ void cp16(unsigned dst, const void* src) {
    asm volatile("cp.async.cg.shared.global [%0], [%1], 16;\n"
                 :: "r"(dst), "l"(src));
}

#define MMA_TF32(d0,d1,d2,d3,a0,a1,a2,a3,b0,b1) \
    asm volatile( \
        "mma.sync.aligned.m16n8k8.row.col.f32.tf32.tf32.f32 " \
        "{%0,%1,%2,%3}, {%4,%5,%6,%7}, {%8,%9}, {%0,%1,%2,%3};\n" \
        : "+f"(d0), "+f"(d1), "+f"(d2), "+f"(d3) \
        : "r"(a0), "r"(a1), "r"(a2), "r"(a3), "r"(b0), "r"(b1))

#define MMA_F16(d0,d1,d2,d3,a0,a1,a2,a3,b0,b1) \
    asm volatile( \
        "mma.sync.aligned.m16n8k16.row.col.f32.f16.f16.f32 " \
        "{%0,%1,%2,%3}, {%4,%5,%6,%7}, {%8,%9}, {%0,%1,%2,%3};\n" \
        : "+f"(d0), "+f"(d1), "+f"(d2), "+f"(d3) \
        : "r"(a0), "r"(a1), "r"(a2), "r"(a3), "r"(b0), "r"(b1))

// ---------------- fp32 -> fp16 conversions ---------------------------------
__global__ __launch_bounds__(256) void h_convert(const float* __restrict__ x,
                                                 __half* __restrict__ y)
{
    size_t i = ((size_t)blockIdx.x * 256 + threadIdx.x) * 8;
    float4 v0 = *(const float4*)(x + i);
    float4 v1 = *(const float4*)(x + i + 4);
    unsigned u0 = ((unsigned)__half_as_ushort(__float2half_rn(v0.y)) << 16) |
                  __half_as_ushort(__float2half_rn(v0.x));
    unsigned u1 = ((unsigned)__half_as_ushort(__float2half_rn(v0.w)) << 16) |
                  __half_as_ushort(__float2half_rn(v0.z));
    unsigned u2 = ((unsigned)__half_as_ushort(__float2half_rn(v1.y)) << 16) |
                  __half_as_ushort(__float2half_rn(v1.x));
    unsigned u3 = ((unsigned)__half_as_ushort(__float2half_rn(v1.w)) << 16) |
                  __half_as_ushort(__float2half_rn(v1.z));
    uint4 o; o.x = u0; o.y = u1; o.z = u2; o.w = u3;
    *(uint4*)(y + i) = o;
}

// transpose + convert: W[K][N] fp32 -> Wt[N][K] half. z==1 -> (W2, T2).
__global__ __launch_bounds__(256) void t_convert(
    const float* __restrict__ W, __half* __restrict__ T, int K, int N,
    const float* __restrict__ W2, __half* __restrict__ T2)
{
    if (blockIdx.z == 1) { W = W2; T = T2; }
    __shared__ float ts[32][33];
    const int tx = threadIdx.x & 31;
    const int ty = threadIdx.x >> 5;         // 0..7
    const int n0 = blockIdx.x * 32;
    const int k0 = blockIdx.y * 32;
#pragma unroll
    for (int i = 0; i < 4; i++)
        ts[ty + i * 8][tx] = W[(size_t)(k0 + ty + i * 8) * N + n0 + tx];
    __syncthreads();
#pragma unroll
    for (int i = 0; i < 4; i++) {
        int n = n0 + ty + i * 8;
        T[(size_t)n * K + k0 + tx] = __float2half_rn(ts[tx][ty + i * 8]);
    }
}

// ============ fp16 tensor-core GEMM: C[M,N] = A[M,K] @ Bt[N,K]^T ===========
// CTA 128x128x32, 8 warps (warp 64x32), 3-stage cp.async pipeline.
// A, Bt are half; both tiles stored [row][k] with 40-half stride.
#define TBM 128
#define TBN 128
#define TBK 32                         // halves per k-chunk
#define NST 3
#define HSTR 40                        // tile row stride in halves (20 words)
#define TILE_H (128 * HSTR)            // 5120 halves per tile
#define STG_H (2 * TILE_H)             // 10240 halves per stage (20480 B)
#define GEMM_SMEM (NST * STG_H * 2)    // 61440 B

__global__ __launch_bounds__(256) void gemm_f16(
    const __half* __restrict__ A, const __half* __restrict__ B,
    float* __restrict__ C, const __half* __restrict__ B2,
    float* __restrict__ C2, int M, int N, int K, int rnd)
{
    extern __shared__ char gsmc[];
    unsigned short* sm16 = (unsigned short*)gsmc;

    if (blockIdx.z == 1) { B = B2; C = C2; }

    const int tid    = threadIdx.x;
    const int lane   = tid & 31;
    const int wid    = tid >> 5;
    const int warp_m = (wid >> 2) * 64;     // 0, 64
    const int warp_n = (wid & 3)  * 32;     // 0,32,64,96
    const int grp    = lane >> 2;
    const int tg     = lane & 3;

    const int m0 = blockIdx.y * TBM;
    const int n0 = blockIdx.x * TBN;

    // loader: 2 A-chunks + 2 B-chunks of 16B (8 halves) per thread per stage
    const int q0 = tid * 2;
    const int r0 = q0 >> 2,       c0 = (q0 & 3) * 8;
    const int r1 = (q0+1) >> 2,   c1 = ((q0+1) & 3) * 8;

    const unsigned smem_base = (unsigned)__cvta_generic_to_shared(sm16);

    float acc[4][4][4];
#pragma unroll
    for (int i = 0; i < 4; i++)
#pragma unroll
        for (int j = 0; j < 4; j++)
#pragma unroll
            for (int c = 0; c < 4; c++) acc[i][j][c] = 0.0f;

    const int niter = K / TBK;

#pragma unroll
    for (int s = 0; s < NST - 1; s++) {
        int k0 = s * TBK;
        unsigned as = smem_base + (s * STG_H) * 2;
        unsigned bs = as + TILE_H * 2;
        cp16(as + (r0 * HSTR + c0) * 2, A + (size_t)(m0 + r0) * K + k0 + c0);
        cp16(as + (r1 * HSTR + c1) * 2, A + (size_t)(m0 + r1) * K + k0 + c1);
        cp16(bs + (r0 * HSTR + c0) * 2, B + (size_t)(n0 + r0) * K + k0 + c0);
        cp16(bs + (r1 * HSTR + c1) * 2, B + (size_t)(n0 + r1) * K + k0 + c1);
        asm volatile("cp.async.commit_group;\n");
    }

    for (int it = 0; it < niter; it++) {
        if (it + NST - 1 < niter) {
            int k0 = (it + NST - 1) * TBK;
            int st = (it + NST - 1) % NST;
            unsigned as = smem_base + (st * STG_H) * 2;
            unsigned bs = as + TILE_H * 2;
            cp16(as + (r0 * HSTR + c0) * 2, A + (size_t)(m0 + r0) * K + k0 + c0);
            cp16(as + (r1 * HSTR + c1) * 2, A + (size_t)(m0 + r1) * K + k0 + c1);
            cp16(bs + (r0 * HSTR + c0) * 2, B + (size_t)(n0 + r0) * K + k0 + c0);
            cp16(bs + (r1 * HSTR + c1) * 2, B + (size_t)(n0 + r1) * K + k0 + c1);
        }
        asm volatile("cp.async.commit_group;\n");
        asm volatile("cp.async.wait_group 2;\n");
        __syncthreads();

        const unsigned short* As = sm16 + (it % NST) * STG_H;
        const unsigned short* Bs = As + TILE_H;

#pragma unroll
        for (int ks = 0; ks < 2; ks++) {          // two k16 sub-steps
            const int kh = ks * 16;
            unsigned a[4][4], bfr[4][2];
#pragma unroll
            for (int mi = 0; mi < 4; mi++) {
                int mb = warp_m + mi * 16;
                a[mi][0] = *(const unsigned*)&As[(mb + grp)     * HSTR + kh + 2*tg];
                a[mi][1] = *(const unsigned*)&As[(mb + grp + 8) * HSTR + kh + 2*tg];
                a[mi][2] = *(const unsigned*)&As[(mb + grp)     * HSTR + kh + 2*tg + 8];
                a[mi][3] = *(const unsigned*)&As[(mb + grp + 8) * HSTR + kh + 2*tg + 8];
            }
#pragma unroll
            for (int nj = 0; nj < 4; nj++) {
                int nb = warp_n + nj * 8;
                bfr[nj][0] = *(const unsigned*)&Bs[(nb + grp) * HSTR + kh + 2*tg];
                bfr[nj][1] = *(const unsigned*)&Bs[(nb + grp) * HSTR + kh + 2*tg + 8];
            }
#pragma unroll
            for (int mi = 0; mi < 4; mi++)
#pragma unroll
                for (int nj = 0; nj < 4; nj++)
                    MMA_F16(acc[mi][nj][0], acc[mi][nj][1], acc[mi][nj][2], acc[mi][nj][3],
                            a[mi][0], a[mi][1], a[mi][2], a[mi][3],
                            bfr[nj][0], bfr[nj][1]);
        }
        __syncthreads();
    }

#pragma unroll
    for (int mi = 0; mi < 4; mi++)
#pragma unroll
        for (int nj = 0; nj < 4; nj++) {
            int row = m0 + warp_m + mi * 16 + grp;
            int col = n0 + warp_n + nj * 8 + 2 * tg;
            float v0 = acc[mi][nj][0], v1 = acc[mi][nj][1];
            float v2 = acc[mi][nj][2], v3 = acc[mi][nj][3];
            if (rnd) {
                v0 = __uint_as_float(f2tf32(v0));
                v1 = __uint_as_float(f2tf32(v1));
                v2 = __uint_as_float(f2tf32(v2));
                v3 = __uint_as_float(f2tf32(v3));
            }
            *(float2*)(C + (size_t)row * N + col)       = make_float2(v0, v1);
            *(float2*)(C + (size_t)(row + 8) * N + col) = make_float2(v2, v3);
        }
}

// ---------------- RoPE: warp-per-head, lane owns (j, j+32) pair ------------
__global__ __launch_bounds__(256) void rope_kernel(const float* __restrict__ cosb,
                                                   const float* __restrict__ sinb)
{
    const int t    = blockIdx.x;
    const int lane = threadIdx.x & 31;
    const int w    = threadIdx.x >> 5;

    const float c0 = cosb[(size_t)t * ROT + lane];
    const float c1 = cosb[(size_t)t * ROT + 32 + lane];
    const float s0 = sinb[(size_t)t * ROT + lane];
    const float s1 = sinb[(size_t)t * ROT + 32 + lane];

#pragma unroll
    for (int head = w; head < NH + NKV; head += 8) {
        float* base = (head < NH)
            ? g_qg + (size_t)t * QGN + head * HD
            : g_k  + (size_t)t * KVN + (head - NH) * HD;
        float x0 = base[lane];
        float x1 = base[lane + 32];
        float p0 = base[64 + lane];
        float p1 = base[96 + lane];
        float rh0 = -x1;
        float rh1 = x0;
        if (head < NH) {
            base[lane]      = c0 * p0 + rh0 * s0;
            base[lane + 32] = c1 * p1 + rh1 * s1;
        } else {
            base[lane]      = __uint_as_float(f2tf32(s0 * p0 + rh0 * s0));
            base[lane + 32] = __uint_as_float(f2tf32(s1 * p1 + rh1 * s1));
        }
    }
}

// =============== flash attention, tf32 tensor cores (R11, unchanged) =======
#define TSTR 136
#define QTILE (128 * TSTR)
#define KVTILE (64 * TSTR)
#define ATT_SMEM ((QTILE + 2 * 2 * KVTILE) * 4)   // 208896 B

__global__ __launch_bounds__(256) void attn_mma_kernel()
{
    extern __shared__ float sm[];

    const int qt  = (int)gridDim.x - 1 - (int)blockIdx.x;
    const int h   = blockIdx.y;
    const int b   = blockIdx.z;
    const int kvh = h / (NH / NKV);

    const int tid  = threadIdx.x;
    const int lane = tid & 31;
    const int wid  = tid >> 5;
    const int grp  = lane >> 2;
    const int tg   = lane & 3;
    const int wm   = wid * 16;

    const unsigned smb = (unsigned)__cvta_generic_to_shared(sm);
    const int njt = 2 * qt + 2;

    const float* Qb = g_qg + (size_t)(b * SEQ + qt * 128) * QGN + h * HD;
#pragma unroll
    for (int i = 0; i < 16; i++) {
        int c = tid + i * 256;
        int r = c >> 5;
        int cl = (c & 31) * 4;
        cp16(smb + (r * TSTR + cl) * 4, Qb + (size_t)r * QGN + cl);
    }
    {
        const float* Kb = g_k + (size_t)(b * SEQ) * KVN + kvh * HD;
        const float* Vb = g_v + (size_t)(b * SEQ) * KVN + kvh * HD;
#pragma unroll
        for (int i = 0; i < 8; i++) {
            int c = tid + i * 256;
            int r = c >> 5;
            int cl = (c & 31) * 4;
            cp16(smb + (QTILE + r * TSTR + cl) * 4,          Kb + (size_t)r * KVN + cl);
            cp16(smb + (QTILE + KVTILE + r * TSTR + cl) * 4, Vb + (size_t)r * KVN + cl);
        }
    }
    asm volatile("cp.async.commit_group;\n");

    float o[16][4];
#pragma unroll
    for (int nt = 0; nt < 16; nt++)
#pragma unroll
        for (int c = 0; c < 4; c++) o[nt][c] = 0.0f;
    float m0 = -1e30f, m1 = -1e30f, l0 = 0.0f, l1 = 0.0f;
    unsigned qf[16][4];

    const float scale = 0.08838834764831845f;
    const int row_g0 = qt * 128 + wm + grp;
    const int row_g1 = row_g0 + 8;
    const unsigned src_lo = (unsigned)((lane & ~3) | (tg >> 1));
    const unsigned src_hi = src_lo | 2u;
    const bool odd = (tg & 1);

    for (int jt = 0; jt < njt; jt++) {
        const int cs = jt & 1;
        if (jt + 1 < njt) {
            const int ns = 1 - cs;
            const float* Kb = g_k + (size_t)(b * SEQ + (jt + 1) * 64) * KVN + kvh * HD;
            const float* Vb = g_v + (size_t)(b * SEQ + (jt + 1) * 64) * KVN + kvh * HD;
            unsigned kofs = smb + (QTILE + ns * 2 * KVTILE) * 4;
#pragma unroll
            for (int i = 0; i < 8; i++) {
                int c = tid + i * 256;
                int r = c >> 5;
                int cl = (c & 31) * 4;
                cp16(kofs + (r * TSTR + cl) * 4,          Kb + (size_t)r * KVN + cl);
                cp16(kofs + (KVTILE + r * TSTR + cl) * 4, Vb + (size_t)r * KVN + cl);
            }
        }
        asm volatile("cp.async.commit_group;\n");
        asm volatile("cp.async.wait_group 1;\n");
        __syncthreads();

        const float* Ks = sm + QTILE + cs * 2 * KVTILE;
        const float* Vs = Ks + KVTILE;

        if (jt == 0) {
            const float* Qs = sm;
#pragma unroll
            for (int ks = 0; ks < 16; ks++) {
                int k0 = ks * 8;
                qf[ks][0] = f2tf32(Qs[(wm + grp)     * TSTR + k0 + tg]);
                qf[ks][1] = f2tf32(Qs[(wm + grp + 8) * TSTR + k0 + tg]);
                qf[ks][2] = f2tf32(Qs[(wm + grp)     * TSTR + k0 + tg + 4]);
                qf[ks][3] = f2tf32(Qs[(wm + grp + 8) * TSTR + k0 + tg + 4]);
            }
        }

        float s[8][4];
#pragma unroll
        for (int nt = 0; nt < 8; nt++)
#pragma unroll
            for (int c = 0; c < 4; c++) s[nt][c] = 0.0f;

#pragma unroll
        for (int ks = 0; ks < 16; ks++) {
            int k0 = ks * 8;
#pragma unroll
            for (int nt = 0; nt < 8; nt++) {
                unsigned b0 = __float_as_uint(Ks[(nt * 8 + grp) * TSTR + k0 + tg]);
                unsigned b1 = __float_as_uint(Ks[(nt * 8 + grp) * TSTR + k0 + tg + 4]);
                MMA_TF32(s[nt][0], s[nt][1], s[nt][2], s[nt][3],
                         qf[ks][0], qf[ks][1], qf[ks][2], qf[ks][3], b0, b1);
            }
        }

        const bool need_mask = (jt >= 2 * qt);
#pragma unroll
        for (int nt = 0; nt < 8; nt++) {
            s[nt][0] *= scale; s[nt][1] *= scale;
            s[nt][2] *= scale; s[nt][3] *= scale;
            if (need_mask) {
                int c0 = jt * 64 + nt * 8 + 2 * tg;
                if (c0     > row_g0) s[nt][0] = -1.0e9f;
                if (c0 + 1 > row_g0) s[nt][1] = -1.0e9f;
                if (c0     > row_g1) s[nt][2] = -1.0e9f;
                if (c0 + 1 > row_g1) s[nt][3] = -1.0e9f;
            }
        }

        float mx0 = -1e30f, mx1 = -1e30f;
#pragma unroll
        for (int nt = 0; nt < 8; nt++) {
            mx0 = fmaxf(mx0, fmaxf(s[nt][0], s[nt][1]));
            mx1 = fmaxf(mx1, fmaxf(s[nt][2], s[nt][3]));
        }
        mx0 = fmaxf(mx0, __shfl_xor_sync(0xffffffffu, mx0, 1));
        mx0 = fmaxf(mx0, __shfl_xor_sync(0xffffffffu, mx0, 2));
        mx1 = fmaxf(mx1, __shfl_xor_sync(0xffffffffu, mx1, 1));
        mx1 = fmaxf(mx1, __shfl_xor_sync(0xffffffffu, mx1, 2));

        float mn0 = fmaxf(m0, mx0);
        float mn1 = fmaxf(m1, mx1);
        float sc0 = __expf(m0 - mn0);
        float sc1 = __expf(m1 - mn1);
        float rs0 = 0.0f, rs1 = 0.0f;
#pragma unroll
        for (int nt = 0; nt < 8; nt++) {
            s[nt][0] = __expf(s[nt][0] - mn0);
            s[nt][1] = __expf(s[nt][1] - mn0);
            s[nt][2] = __expf(s[nt][2] - mn1);
            s[nt][3] = __expf(s[nt][3] - mn1);
            rs0 += s[nt][0] + s[nt][1];
            rs1 += s[nt][2] + s[nt][3];
        }
        rs0 += __shfl_xor_sync(0xffffffffu, rs0, 1);
        rs0 += __shfl_xor_sync(0xffffffffu, rs0, 2);
        rs1 += __shfl_xor_sync(0xffffffffu, rs1, 1);
        rs1 += __shfl_xor_sync(0xffffffffu, rs1, 2);

        l0 = l0 * sc0 + rs0; m0 = mn0;
        l1 = l1 * sc1 + rs1; m1 = mn1;
#pragma unroll
        for (int nt = 0; nt < 16; nt++) {
            o[nt][0] *= sc0; o[nt][1] *= sc0;
            o[nt][2] *= sc1; o[nt][3] *= sc1;
        }

        unsigned u[8][4];
#pragma unroll
        for (int nt = 0; nt < 8; nt++)
#pragma unroll
            for (int c = 0; c < 4; c++) u[nt][c] = f2tf32(s[nt][c]);

#pragma unroll
        for (int ks = 0; ks < 8; ks++) {
            unsigned t00 = __shfl_sync(0xffffffffu, u[ks][0], src_lo);
            unsigned t01 = __shfl_sync(0xffffffffu, u[ks][1], src_lo);
            unsigned a0  = odd ? t01 : t00;
            unsigned t10 = __shfl_sync(0xffffffffu, u[ks][2], src_lo);
            unsigned t11 = __shfl_sync(0xffffffffu, u[ks][3], src_lo);
            unsigned a1  = odd ? t11 : t10;
            unsigned t20 = __shfl_sync(0xffffffffu, u[ks][0], src_hi);
            unsigned t21 = __shfl_sync(0xffffffffu, u[ks][1], src_hi);
            unsigned a2  = odd ? t21 : t20;
            unsigned t30 = __shfl_sync(0xffffffffu, u[ks][2], src_hi);
            unsigned t31 = __shfl_sync(0xffffffffu, u[ks][3], src_hi);
            unsigned a3  = odd ? t31 : t30;
            int k0 = ks * 8;
#pragma unroll
            for (int nt = 0; nt < 16; nt++) {
                unsigned b0 = __float_as_uint(Vs[(k0 + tg)     * TSTR + nt * 8 + grp]);
                unsigned b1 = __float_as_uint(Vs[(k0 + tg + 4) * TSTR + nt * 8 + grp]);
                MMA_TF32(o[nt][0], o[nt][1], o[nt][2], o[nt][3], a0, a1, a2, a3, b0, b1);
            }
        }
        __syncthreads();
    }

    float inv0 = 1.0f / l0;
    float inv1 = 1.0f / l1;
#pragma unroll
    for (int nt = 0; nt < 16; nt++) {
        int col = h * HD + nt * 8 + 2 * tg;
        *(float2*)(g_o + (size_t)(b * SEQ + row_g0) * HID + col) =
            make_float2(o[nt][0] * inv0, o[nt][1] * inv0);
        *(float2*)(g_o + (size_t)(b * SEQ + row_g1) * HID + col) =
            make_float2(o[nt][2] * inv1, o[nt][3] * inv1);
    }
}

// ------ rmsnorm * (1+w) * sigmoid(gate); emits half for Wo GEMM ------------
__global__ __launch_bounds__(256) void norm_gate_kernel(const float* __restrict__ nw)
{
    const int t   = blockIdx.x;
    const int tid = threadIdx.x;
    const float* o    = g_o  + (size_t)t * HID;
    const float* gate = g_qg + (size_t)t * QGN + 2048;

    float vals[8];
    float ss = 0.0f;
#pragma unroll
    for (int i = 0; i < 8; i++) {
        float v = o[tid + i * 256];
        vals[i] = v;
        ss += v * v;
    }
#pragma unroll
    for (int off = 16; off >= 1; off >>= 1)
        ss += __shfl_xor_sync(0xffffffffu, ss, off);

    __shared__ float red[8];
    if ((tid & 31) == 0) red[tid >> 5] = ss;
    __syncthreads();
    float tot = red[0] + red[1] + red[2] + red[3] + red[4] + red[5] + red[6] + red[7];
    float r = rsqrtf(tot / (float)HID + 1e-6f);

#pragma unroll
    for (int i = 0; i < 8; i++) {
        int j = tid + i * 256;
        float gt = gate[j];
        float sg = 1.0f / (1.0f + __expf(-gt));
        g_nh[(size_t)t * HID + j] =
            __float2half_rn(vals[i] * r * (1.0f + nw[j]) * sg);
    }
}

// ---------------- launch ---------------------------------------------------
extern "C" void kernel_launch(void* const* d_in, const int* in_sizes, int n_in,
                              void* d_out, int out_size)
{
    const float* hs   = (const float*)d_in[0];
    const float* cosb = (const float*)d_in[1];
    const float* sinb = (const float*)d_in[2];
    // d_in[3] = attention_mask (causal, reproduced analytically)
    const float* Wq   = (const float*)d_in[4];
    const float* Wk   = (const float*)d_in[5];
    const float* Wv   = (const float*)d_in[6];
    const float* Wo   = (const float*)d_in[7];
    const float* nw   = (const float*)d_in[8];
    float* out = (float*)d_out;

    float *qg, *kb, *vb;
    __half *hsh, *wqt, *wkt, *wvt, *wot, *nh;
    cudaGetSymbolAddress((void**)&qg,  g_qg);
    cudaGetSymbolAddress((void**)&kb,  g_k);
    cudaGetSymbolAddress((void**)&vb,  g_v);
    cudaGetSymbolAddress((void**)&hsh, g_hsh);
    cudaGetSymbolAddress((void**)&wqt, g_wqt);
    cudaGetSymbolAddress((void**)&wkt, g_wkt);
    cudaGetSymbolAddress((void**)&wvt, g_wvt);
    cudaGetSymbolAddress((void**)&wot, g_wot);
    cudaGetSymbolAddress((void**)&nh,  g_nh);

    dim3 blk(256);

    cudaFuncSetAttribute(gemm_f16, cudaFuncAttributeMaxDynamicSharedMemorySize, GEMM_SMEM);
    cudaFuncSetAttribute(attn_mma_kernel, cudaFuncAttributeMaxDynamicSharedMemorySize, ATT_SMEM);

    // 0) convert hs -> half; transpose+convert weights -> half [N][K]
    h_convert<<<(NTOK * (size_t)HID) / 2048, blk>>>(hs, hsh);
    t_convert<<<dim3(QGN / 32, HID / 32, 1), blk>>>(Wq, wqt, HID, QGN, Wq, wqt);
    t_convert<<<dim3(KVN / 32, HID / 32, 2), blk>>>(Wk, wkt, HID, KVN, Wv, wvt);
    t_convert<<<dim3(HID / 32, HID / 32, 1), blk>>>(Wo, wot, HID, HID, Wo, wot);

    // 1) projections (fp16 mma, m16n8k16); KV outputs tf32-rounded
    gemm_f16<<<dim3(QGN / TBN, NTOK / TBM, 1), blk, GEMM_SMEM>>>(
        hsh, wqt, qg, wqt, qg, NTOK, QGN, HID, 0);
    gemm_f16<<<dim3(KVN / TBN, NTOK / TBM, 2), blk, GEMM_SMEM>>>(
        hsh, wkt, kb, wvt, vb, NTOK, KVN, HID, 1);

    // 2) rope (K outputs tf32-rounded)
    rope_kernel<<<NTOK, blk>>>(cosb, sinb);

    // 3) flash attention (tf32, unchanged)
    attn_mma_kernel<<<dim3(SEQ / 128, NH, BATCH), blk, ATT_SMEM>>>();

    // 4) rmsnorm * sigmoid(gate) -> half activations
    norm_gate_kernel<<<NTOK, blk>>>(nw);

    // 5) output projection (fp16 mma)
    gemm_f16<<<dim3(HID / TBN, NTOK / TBM, 1), blk, GEMM_SMEM>>>(
        nh, wot, out, wot, out, NTOK, HID, HID, 0);
}